// round 5
// baseline (speedup 1.0000x reference)
#include <cuda_runtime.h>

// Problem shape (fixed by reference setup_inputs)
#define B_     8
#define NENS   16
#define C_     4
#define H_     128
#define W_     256
#define CHW    (C_*H_*W_)          // 131072 floats per (b,n) plane
#define CHW2   (CHW/2)             // 65536 float2
#define POS_TOTAL (B_*CHW)         // 1048576 positions
#define V2TOTAL   (POS_TOTAL/2)    // 524288 float2 groups
#define THREADS 256
#define GRID    296                 // 2 CTAs per SM (148 SMs), persistent
#define STRIDE  (GRID*THREADS)      // 75776

__device__ float        g_partials[GRID];
__device__ unsigned int g_count = 0;   // wraps to 0 every launch via atomicInc

// Optimal 60-comparator sorting network for 16 inputs (Green's network).
#define CE(i, j) { float _a = x[i], _b = x[j]; x[i] = fminf(_a, _b); x[j] = fmaxf(_a, _b); }
__device__ __forceinline__ void sort16(float x[16]) {
    CE(0,1) CE(2,3) CE(4,5) CE(6,7) CE(8,9) CE(10,11) CE(12,13) CE(14,15)
    CE(0,2) CE(4,6) CE(8,10) CE(12,14) CE(1,3) CE(5,7) CE(9,11) CE(13,15)
    CE(0,4) CE(8,12) CE(1,5) CE(9,13) CE(2,6) CE(10,14) CE(3,7) CE(11,15)
    CE(0,8) CE(1,9) CE(2,10) CE(3,11) CE(4,12) CE(5,13) CE(6,14) CE(7,15)
    CE(5,10) CE(6,9) CE(3,12) CE(13,14) CE(7,11) CE(1,2) CE(4,8)
    CE(1,4) CE(7,13) CE(2,8) CE(11,14) CE(5,6) CE(9,10)
    CE(2,4) CE(11,13) CE(3,8) CE(7,12)
    CE(6,8) CE(10,12) CE(3,5) CE(7,9)
    CE(3,4) CE(5,6) CE(7,8) CE(9,10) CE(11,12)
    CE(6,7) CE(8,9)
}
#undef CE

__device__ __forceinline__ void load_tile(const float2* __restrict__ p2,
                                          const float2* __restrict__ gt2,
                                          int idx, float2 p[NENS], float2& g) {
    const int b   = idx >> 16;            // idx / CHW2
    const int rem = idx & (CHW2 - 1);     // idx % CHW2
    const int pbase = b * (NENS * CHW2) + rem;
#pragma unroll
    for (int n = 0; n < NENS; n++)
        p[n] = __ldcs(&p2[pbase + n * CHW2]);
    g = __ldcs(&gt2[idx]);
}

__device__ __forceinline__ float tile_crps(const float2 p[NENS], float2 g) {
    float acc = 0.0f;
#pragma unroll
    for (int s = 0; s < 2; s++) {
        const float gv = (s == 0) ? g.x : g.y;
        float x[NENS];
#pragma unroll
        for (int n = 0; n < NENS; n++)
            x[n] = (s == 0) ? p[n].x : p[n].y;

        // term1 * N (order-independent; before sort)
        float t1 = 0.0f;
#pragma unroll
        for (int n = 0; n < NENS; n++)
            t1 += fabsf(x[n] - gv);

        sort16(x);

        // sum_{i<j}(x_(j) - x_(i)) = sum_i (2i-15) * x_sorted_i
        float ws = 0.0f;
#pragma unroll
        for (int n = 0; n < NENS; n++)
            ws = fmaf((float)(2 * n - (NENS - 1)), x[n], ws);

        acc += t1 * (1.0f / NENS) - ws * (1.0f / (NENS * (NENS - 1)));
    }
    return acc;
}

__global__ void __launch_bounds__(THREADS, 2)
crps_fused(const float* __restrict__ preds, const float* __restrict__ gt,
           float* __restrict__ out) {
    const float2* __restrict__ gt2 = (const float2*)gt;
    const float2* __restrict__ p2  = (const float2*)preds;

    int idx = blockIdx.x * THREADS + threadIdx.x;   // float2-group id
    float acc = 0.0f;

    // -- software-pipelined grid-stride loop: prefetch next tile during compute --
    float2 p[NENS], g;
    load_tile(p2, gt2, idx, p, g);                  // prologue

    while (true) {
        const int next = idx + STRIDE;
        const bool has_next = (next < V2TOTAL);

        float2 pn[NENS], gn;
        if (has_next)
            load_tile(p2, gt2, next, pn, gn);       // in flight during compute below

        acc += tile_crps(p, g);

        if (!has_next) break;
#pragma unroll
        for (int n = 0; n < NENS; n++) p[n] = pn[n];
        g = gn;
        idx = next;
    }

    // ---- deterministic block reduction ----
    __shared__ float warp_sums[THREADS / 32];
    const int lane = threadIdx.x & 31;
    const int wid  = threadIdx.x >> 5;
#pragma unroll
    for (int off = 16; off > 0; off >>= 1)
        acc += __shfl_down_sync(0xffffffffu, acc, off);
    if (lane == 0) warp_sums[wid] = acc;
    __syncthreads();

    __shared__ bool is_last;
    if (threadIdx.x == 0) {
        float v = 0.0f;
#pragma unroll
        for (int w = 0; w < THREADS / 32; w++) v += warp_sums[w];
        g_partials[blockIdx.x] = v;
        __threadfence();
        unsigned int old = atomicInc(&g_count, GRID - 1);  // wraps to 0 -> self-reset
        is_last = (old == GRID - 1);
    }
    __syncthreads();

    // ---- last block finalizes (fixed-order tree -> deterministic) ----
    if (is_last) {
        const volatile float* vp = (const volatile float*)g_partials;
        float v = 0.0f;
#pragma unroll
        for (int k = 0; k < 2; k++) {                 // covers 296 <= 2*256
            int j = threadIdx.x + k * THREADS;
            if (j < GRID) v += vp[j];
        }
#pragma unroll
        for (int off = 16; off > 0; off >>= 1)
            v += __shfl_down_sync(0xffffffffu, v, off);
        if (lane == 0) warp_sums[wid] = v;
        __syncthreads();
        if (wid == 0) {
            float t = (lane < THREADS / 32) ? warp_sums[lane] : 0.0f;
#pragma unroll
            for (int off = 4; off > 0; off >>= 1)
                t += __shfl_down_sync(0xffffffffu, t, off);
            if (lane == 0) out[0] = t * (1.0f / (float)POS_TOTAL);
        }
    }
}

extern "C" void kernel_launch(void* const* d_in, const int* in_sizes, int n_in,
                              void* d_out, int out_size) {
    const float* preds = (const float*)d_in[0];
    const float* gt    = (const float*)d_in[1];
    crps_fused<<<GRID, THREADS>>>(preds, gt, (float*)d_out);
}

// round 8
// speedup vs baseline: 1.0342x; 1.0342x over previous
#include <cuda_runtime.h>

// Problem shape (fixed by reference setup_inputs)
#define B_     8
#define NENS   16
#define C_     4
#define H_     128
#define W_     256
#define CHW    (C_*H_*W_)          // 131072 floats per (b,n) plane
#define CHW2   (CHW/2)             // 65536 float2
#define POS_TOTAL (B_*CHW)         // 1048576 positions
#define V2TOTAL   (POS_TOTAL/2)    // 524288 float2 groups
#define THREADS 256
#define GRID    592                 // 148 SMs x 4 CTAs, all co-resident
#define STRIDE  (GRID*THREADS)      // 151552

__device__ float        g_partials[GRID];
__device__ unsigned int g_count = 0;   // wraps to 0 every launch via atomicInc

__device__ __forceinline__ void prefetch_l2(const void* p) {
    asm volatile("prefetch.global.L2 [%0];" :: "l"(p));
}

// Optimal 60-comparator sorting network for 16 inputs (Green's network).
#define CE(i, j) { float _a = x[i], _b = x[j]; x[i] = fminf(_a, _b); x[j] = fmaxf(_a, _b); }
__device__ __forceinline__ void sort16(float x[16]) {
    CE(0,1) CE(2,3) CE(4,5) CE(6,7) CE(8,9) CE(10,11) CE(12,13) CE(14,15)
    CE(0,2) CE(4,6) CE(8,10) CE(12,14) CE(1,3) CE(5,7) CE(9,11) CE(13,15)
    CE(0,4) CE(8,12) CE(1,5) CE(9,13) CE(2,6) CE(10,14) CE(3,7) CE(11,15)
    CE(0,8) CE(1,9) CE(2,10) CE(3,11) CE(4,12) CE(5,13) CE(6,14) CE(7,15)
    CE(5,10) CE(6,9) CE(3,12) CE(13,14) CE(7,11) CE(1,2) CE(4,8)
    CE(1,4) CE(7,13) CE(2,8) CE(11,14) CE(5,6) CE(9,10)
    CE(2,4) CE(11,13) CE(3,8) CE(7,12)
    CE(6,8) CE(10,12) CE(3,5) CE(7,9)
    CE(3,4) CE(5,6) CE(7,8) CE(9,10) CE(11,12)
    CE(6,7) CE(8,9)
}
#undef CE

__device__ __forceinline__ float tile_crps(const float2* __restrict__ p2,
                                           const float2* __restrict__ gt2,
                                           int idx, int next_idx, bool has_next) {
    const int b   = idx >> 16;            // idx / CHW2
    const int rem = idx & (CHW2 - 1);     // idx % CHW2
    const int pbase = b * (NENS * CHW2) + rem;

    // 16 independent float2 loads (expected L2-hit thanks to prefetch)
    float2 p[NENS];
#pragma unroll
    for (int n = 0; n < NENS; n++)
        p[n] = __ldg(&p2[pbase + n * CHW2]);
    const float2 g = __ldg(&gt2[idx]);

    // fire-and-forget prefetch of the NEXT tile into L2 (no regs consumed)
    if (has_next) {
        const int nb   = next_idx >> 16;
        const int nrem = next_idx & (CHW2 - 1);
        const int npbase = nb * (NENS * CHW2) + nrem;
#pragma unroll
        for (int n = 0; n < NENS; n++)
            prefetch_l2(&p2[npbase + n * CHW2]);
        prefetch_l2(&gt2[next_idx]);
    }

    float acc = 0.0f;
#pragma unroll
    for (int s = 0; s < 2; s++) {
        const float gv = (s == 0) ? g.x : g.y;
        float x[NENS];
#pragma unroll
        for (int n = 0; n < NENS; n++)
            x[n] = (s == 0) ? p[n].x : p[n].y;

        // term1 * N (order-independent; before sort)
        float t1 = 0.0f;
#pragma unroll
        for (int n = 0; n < NENS; n++)
            t1 += fabsf(x[n] - gv);

        sort16(x);

        // sum_{i<j}(x_(j) - x_(i)) = sum_i (2i-15) * x_sorted_i
        float ws = 0.0f;
#pragma unroll
        for (int n = 0; n < NENS; n++)
            ws = fmaf((float)(2 * n - (NENS - 1)), x[n], ws);

        acc += t1 * (1.0f / NENS) - ws * (1.0f / (NENS * (NENS - 1)));
    }
    return acc;
}

__global__ void __launch_bounds__(THREADS, 4)
crps_fused(const float* __restrict__ preds, const float* __restrict__ gt,
           float* __restrict__ out) {
    const float2* __restrict__ gt2 = (const float2*)gt;
    const float2* __restrict__ p2  = (const float2*)preds;

    float acc = 0.0f;
    // grid-stride over float2-groups; 3-4 tiles per thread; prefetch 1 ahead
    for (int idx = blockIdx.x * THREADS + threadIdx.x; idx < V2TOTAL; idx += STRIDE) {
        const int next = idx + STRIDE;
        acc += tile_crps(p2, gt2, idx, next, next < V2TOTAL);
    }

    // ---- deterministic block reduction ----
    __shared__ float warp_sums[THREADS / 32];
    const int lane = threadIdx.x & 31;
    const int wid  = threadIdx.x >> 5;
#pragma unroll
    for (int off = 16; off > 0; off >>= 1)
        acc += __shfl_down_sync(0xffffffffu, acc, off);
    if (lane == 0) warp_sums[wid] = acc;
    __syncthreads();

    __shared__ bool is_last;
    if (threadIdx.x == 0) {
        float v = 0.0f;
#pragma unroll
        for (int w = 0; w < THREADS / 32; w++) v += warp_sums[w];
        g_partials[blockIdx.x] = v;
        __threadfence();
        unsigned int old = atomicInc(&g_count, GRID - 1);  // wraps to 0 -> self-reset
        is_last = (old == GRID - 1);
    }
    __syncthreads();

    // ---- last block finalizes (fixed-order tree -> deterministic) ----
    if (is_last) {
        const volatile float* vp = (const volatile float*)g_partials;
        float v = 0.0f;
#pragma unroll
        for (int k = 0; k < 3; k++) {                 // covers 592 <= 3*256
            int j = threadIdx.x + k * THREADS;
            if (j < GRID) v += vp[j];
        }
#pragma unroll
        for (int off = 16; off > 0; off >>= 1)
            v += __shfl_down_sync(0xffffffffu, v, off);
        if (lane == 0) warp_sums[wid] = v;
        __syncthreads();
        if (wid == 0) {
            float t = (lane < THREADS / 32) ? warp_sums[lane] : 0.0f;
#pragma unroll
            for (int off = 4; off > 0; off >>= 1)
                t += __shfl_down_sync(0xffffffffu, t, off);
            if (lane == 0) out[0] = t * (1.0f / (float)POS_TOTAL);
        }
    }
}

extern "C" void kernel_launch(void* const* d_in, const int* in_sizes, int n_in,
                              void* d_out, int out_size) {
    const float* preds = (const float*)d_in[0];
    const float* gt    = (const float*)d_in[1];
    crps_fused<<<GRID, THREADS>>>(preds, gt, (float*)d_out);
}